// round 6
// baseline (speedup 1.0000x reference)
#include <cuda_runtime.h>
#include <cstdint>

// ---------------------------------------------------------------------------
// Problem constants
// ---------------------------------------------------------------------------
constexpr int    N_USERS = 100000;
constexpr int    DIM     = 128;
constexpr size_t SEG     = (size_t)N_USERS * DIM;
constexpr int    NROWS   = 100000;
constexpr int    NSLOT   = 4;
constexpr int    CAP     = 64;

__device__ float g_scratch[(size_t)NSLOT * NROWS * DIM];
__device__ int  g_cnt[NSLOT * NROWS];
__device__ int2 g_bucket[(size_t)NSLOT * NROWS * CAP];

// ---------------------------------------------------------------------------
// f32x2 packed-FMA helpers
// ---------------------------------------------------------------------------
__device__ __forceinline__ unsigned long long pk2(float x, float y) {
    unsigned long long r;
    asm("mov.b64 %0, {%1, %2};" : "=l"(r) : "r"(__float_as_uint(x)), "r"(__float_as_uint(y)));
    return r;
}
__device__ __forceinline__ unsigned long long fma2(unsigned long long a,
                                                   unsigned long long b,
                                                   unsigned long long c) {
    unsigned long long d;
    asm("fma.rn.f32x2 %0, %1, %2, %3;" : "=l"(d) : "l"(a), "l"(b), "l"(c));
    return d;
}
__device__ __forceinline__ void upk2(unsigned long long v, float& lo, float& hi) {
    uint32_t a, b;
    asm("mov.b64 {%0, %1}, %2;" : "=r"(a), "=r"(b) : "l"(v));
    lo = __uint_as_float(a); hi = __uint_as_float(b);
}

// ---------------------------------------------------------------------------
// Kernel 1: zero counters
// ---------------------------------------------------------------------------
__global__ void zero_cnt() {
    int i = blockIdx.x * blockDim.x + threadIdx.x;
    if (i < NSLOT * NROWS) g_cnt[i] = 0;
}

// ---------------------------------------------------------------------------
// Kernel 2: scatter nnz into per-row buckets (validated R4)
// ---------------------------------------------------------------------------
__global__ void __launch_bounds__(256) scatter_nnz(
    const int* __restrict__ r0, const int* __restrict__ c0, const float* __restrict__ v0,
    const int* __restrict__ r1, const int* __restrict__ c1, const float* __restrict__ v1,
    const int* __restrict__ r2, const int* __restrict__ c2, const float* __restrict__ v2,
    const int* __restrict__ r3, const int* __restrict__ c3, const float* __restrict__ v3,
    int nnz)
{
    const int slot = blockIdx.y;
    const int* rows; const int* cols; const float* vals;
    switch (slot) {
        case 0:  rows = r0; cols = c0; vals = v0; break;
        case 1:  rows = r1; cols = c1; vals = v1; break;
        case 2:  rows = r2; cols = c2; vals = v2; break;
        default: rows = r3; cols = c3; vals = v3; break;
    }
    const int i = blockIdx.x * 256 + threadIdx.x;
    if (i >= nnz) return;
    const int   row = rows[i];
    const int   col = cols[i];
    const float val = vals[i];
    const int gr  = slot * NROWS + row;
    const int pos = atomicAdd(&g_cnt[gr], 1);
    if (pos < CAP)
        g_bucket[(size_t)gr * CAP + pos] = make_int2(col, __float_as_int(val));
}

// ---------------------------------------------------------------------------
// Kernel 3: gather — one warp per output row (validated R4)
// ---------------------------------------------------------------------------
__global__ void __launch_bounds__(256) gather_rows(const float* __restrict__ ebs)
{
    const int wg   = (blockIdx.x * 256 + threadIdx.x) >> 5;
    const int lane = threadIdx.x & 31;
    if (wg >= NSLOT * NROWS) return;

    int cnt = g_cnt[wg];
    cnt = min(cnt, CAP);

    const int2* bk = g_bucket + (size_t)wg * CAP;
    int2 e0 = make_int2(0, 0), e1 = make_int2(0, 0);
    if (lane      < cnt) e0 = bk[lane];
    if (lane + 32 < cnt) e1 = bk[lane + 32];

    float4 acc = make_float4(0.f, 0.f, 0.f, 0.f);
    for (int j = 0; j < cnt; j++) {
        int cj, vb;
        if (j < 32) { cj = __shfl_sync(0xffffffffu, e0.x, j);
                      vb = __shfl_sync(0xffffffffu, e0.y, j); }
        else        { cj = __shfl_sync(0xffffffffu, e1.x, j - 32);
                      vb = __shfl_sync(0xffffffffu, e1.y, j - 32); }
        const float  vj = __int_as_float(vb);
        const float4 e  = *reinterpret_cast<const float4*>(ebs + (size_t)cj * DIM + lane * 4);
        acc.x += vj * e.x; acc.y += vj * e.y; acc.z += vj * e.z; acc.w += vj * e.w;
    }
    *reinterpret_cast<float4*>(g_scratch + (size_t)wg * DIM + lane * 4) = acc;
}

// ---------------------------------------------------------------------------
// Kernel 4: fused fold GEMM + gate + leaky relu, f32x2 FMA.
// Block tile 32 rows x 128 cols, 8 warps in 2x4: warp tile 16 rows x 32 cols.
// Lane (rg = lane&3, cg = lane>>2): 4 rows (rg + 4r, interleaved) x 4 cols.
// Smem rows padded to 132 floats -> the 4 concurrent row reads hit banks
// 0/4/8/12 (conflict-free). W per warp per k: 8 distinct 16B = 1 wavefront.
// ---------------------------------------------------------------------------
constexpr int TR  = 32;     // rows per block
constexpr int PAD = 132;    // floats per padded smem row (528 B, 16B-aligned)

__global__ void __launch_bounds__(256) fold_gemm4(
    const float* __restrict__ ebs,
    const float* __restrict__ Wsu, const float* __restrict__ Wdu,
    const float* __restrict__ Wsi, const float* __restrict__ Wdi,
    float* __restrict__ outp)
{
    __shared__ float As[TR][PAD];   // LI rows
    __shared__ float Bs[TR][PAD];   // (L * ent) rows

    const int fold = blockIdx.y;
    const float* LI  = g_scratch + (size_t)(2 * fold)     * SEG;
    const float* L   = g_scratch + (size_t)(2 * fold + 1) * SEG;
    const float* ent = ebs  + (size_t)fold * SEG;
    const float* Ws  = fold ? Wsi : Wsu;
    const float* Wd  = fold ? Wdi : Wdu;
    float* out       = outp + (size_t)fold * SEG;

    const int row0 = blockIdx.x * TR;
    const int tid  = threadIdx.x;

    // Cooperative load: 32 rows x 128 cols, float4 coalesced.
    for (int i = tid; i < TR * (DIM / 4); i += 256) {
        const int rr = i >> 5;
        const int c4 = i & 31;
        const size_t g = (size_t)(row0 + rr) * DIM + c4 * 4;
        const float4 li = *reinterpret_cast<const float4*>(LI  + g);
        const float4 ll = *reinterpret_cast<const float4*>(L   + g);
        const float4 ee = *reinterpret_cast<const float4*>(ent + g);
        *reinterpret_cast<float4*>(&As[rr][c4 * 4]) = li;
        float4 b = make_float4(ll.x * ee.x, ll.y * ee.y, ll.z * ee.z, ll.w * ee.w);
        *reinterpret_cast<float4*>(&Bs[rr][c4 * 4]) = b;
    }
    __syncthreads();

    const int lane  = tid & 31;
    const int wid   = tid >> 5;
    const int wrow0 = (wid & 1) * 16;      // warp row base (0 or 16)
    const int wcol0 = (wid >> 1) * 32;     // warp col base (0,32,64,96)
    const int rg    = lane & 3;            // row phase: rows wrow0 + rg + 4r
    const int cg    = lane >> 2;           // col group: cols wcol0 + cg*4

    const int colb = wcol0 + cg * 4;       // this lane's 4 output cols

    unsigned long long acc2[4][2];
    #pragma unroll
    for (int r = 0; r < 4; r++) { acc2[r][0] = 0ull; acc2[r][1] = 0ull; }

    #pragma unroll 2
    for (int kb = 0; kb < DIM; kb += 4) {
        // Prefetch W for 4 k: per lane 4 cols = 2 u64 per matrix per k.
        ulonglong2 wsp[4], wdp[4];
        #pragma unroll
        for (int kk = 0; kk < 4; kk++) {
            wsp[kk] = *reinterpret_cast<const ulonglong2*>(Ws + (size_t)(kb + kk) * DIM + colb);
            wdp[kk] = *reinterpret_cast<const ulonglong2*>(Wd + (size_t)(kb + kk) * DIM + colb);
        }
        #pragma unroll
        for (int r = 0; r < 4; r++) {
            const int row = wrow0 + rg + 4 * r;
            const float4 a4 = *reinterpret_cast<const float4*>(&As[row][kb]);
            const float4 b4 = *reinterpret_cast<const float4*>(&Bs[row][kb]);
            const float av[4] = {a4.x, a4.y, a4.z, a4.w};
            const float bv[4] = {b4.x, b4.y, b4.z, b4.w};
            #pragma unroll
            for (int kk = 0; kk < 4; kk++) {
                const unsigned long long aa = pk2(av[kk], av[kk]);
                const unsigned long long bb = pk2(bv[kk], bv[kk]);
                acc2[r][0] = fma2(aa, wsp[kk].x, acc2[r][0]);
                acc2[r][1] = fma2(aa, wsp[kk].y, acc2[r][1]);
                acc2[r][0] = fma2(bb, wdp[kk].x, acc2[r][0]);
                acc2[r][1] = fma2(bb, wdp[kk].y, acc2[r][1]);
            }
        }
    }

    #pragma unroll
    for (int r = 0; r < 4; r++) {
        const int grow = row0 + wrow0 + rg + 4 * r;
        float c0, c1, c2, c3;
        upk2(acc2[r][0], c0, c1);
        upk2(acc2[r][1], c2, c3);
        float4 o;
        o.x = (c0 > 0.f) ? c0 : 0.2f * c0;
        o.y = (c1 > 0.f) ? c1 : 0.2f * c1;
        o.z = (c2 > 0.f) ? c2 : 0.2f * c2;
        o.w = (c3 > 0.f) ? c3 : 0.2f * c3;
        *reinterpret_cast<float4*>(out + (size_t)grow * DIM + colb) = o;
    }
}

// ---------------------------------------------------------------------------
// Launch contract
// ---------------------------------------------------------------------------
extern "C" void kernel_launch(void* const* d_in, const int* in_sizes, int n_in,
                              void* d_out, int out_size)
{
    const float* ebs  = (const float*)d_in[0];
    const float* Wsu  = (const float*)d_in[1];
    const float* Wdu  = (const float*)d_in[2];
    const float* Wsi  = (const float*)d_in[3];
    const float* Wdi  = (const float*)d_in[4];
    const float* vLIu = (const float*)d_in[5];
    const float* vLu  = (const float*)d_in[6];
    const float* vLIi = (const float*)d_in[7];
    const float* vLi  = (const float*)d_in[8];
    const int* rLIu = (const int*)d_in[9];
    const int* cLIu = (const int*)d_in[10];
    const int* rLu  = (const int*)d_in[11];
    const int* cLu  = (const int*)d_in[12];
    const int* rLIi = (const int*)d_in[13];
    const int* cLIi = (const int*)d_in[14];
    const int* rLi  = (const int*)d_in[15];
    const int* cLi  = (const int*)d_in[16];
    float* out = (float*)d_out;

    const int nnz = in_sizes[5];

    // 1) zero counters
    zero_cnt<<<(NSLOT * NROWS + 255) / 256, 256>>>();

    // 2) scatter nnz into buckets
    {
        dim3 grid((nnz + 255) / 256, NSLOT);
        scatter_nnz<<<grid, 256>>>(rLIu, cLIu, vLIu,
                                   rLu,  cLu,  vLu,
                                   rLIi, cLIi, vLIi,
                                   rLi,  cLi,  vLi,
                                   nnz);
    }

    // 3) gather
    {
        const int total_warps = NSLOT * NROWS;
        const int blocks = (total_warps * 32 + 255) / 256;
        gather_rows<<<blocks, 256>>>(ebs);
    }

    // 4) fused fold GEMM, 32-row tiles, 16x32 warp tiles
    {
        dim3 grid(N_USERS / TR, 2);
        fold_gemm4<<<grid, 256>>>(ebs, Wsu, Wdu, Wsi, Wdi, out);
    }
}

// round 8
// speedup vs baseline: 1.1949x; 1.1949x over previous
#include <cuda_runtime.h>
#include <cstdint>

// ---------------------------------------------------------------------------
// Problem constants
// ---------------------------------------------------------------------------
constexpr int    N_USERS = 100000;
constexpr int    DIM     = 128;
constexpr size_t SEG     = (size_t)N_USERS * DIM;
constexpr int    NROWS   = 100000;
constexpr int    NSLOT   = 4;
constexpr int    CAP     = 64;

__device__ float g_scratch[(size_t)NSLOT * NROWS * DIM];
__device__ int  g_cnt[NSLOT * NROWS];
__device__ int2 g_bucket[(size_t)NSLOT * NROWS * CAP];

// ---------------------------------------------------------------------------
// f32x2 packed-FMA helpers
// ---------------------------------------------------------------------------
__device__ __forceinline__ unsigned long long pk2(float x, float y) {
    unsigned long long r;
    asm("mov.b64 %0, {%1, %2};" : "=l"(r) : "r"(__float_as_uint(x)), "r"(__float_as_uint(y)));
    return r;
}
__device__ __forceinline__ unsigned long long fma2(unsigned long long a,
                                                   unsigned long long b,
                                                   unsigned long long c) {
    unsigned long long d;
    asm("fma.rn.f32x2 %0, %1, %2, %3;" : "=l"(d) : "l"(a), "l"(b), "l"(c));
    return d;
}
__device__ __forceinline__ void upk2(unsigned long long v, float& lo, float& hi) {
    uint32_t a, b;
    asm("mov.b64 {%0, %1}, %2;" : "=r"(a), "=r"(b) : "l"(v));
    lo = __uint_as_float(a); hi = __uint_as_float(b);
}

// ---------------------------------------------------------------------------
// Kernel 1: zero counters
// ---------------------------------------------------------------------------
__global__ void zero_cnt() {
    int i = blockIdx.x * blockDim.x + threadIdx.x;
    if (i < NSLOT * NROWS) g_cnt[i] = 0;
}

// ---------------------------------------------------------------------------
// Kernel 2: scatter nnz into per-row buckets (validated R4)
// ---------------------------------------------------------------------------
__global__ void __launch_bounds__(256) scatter_nnz(
    const int* __restrict__ r0, const int* __restrict__ c0, const float* __restrict__ v0,
    const int* __restrict__ r1, const int* __restrict__ c1, const float* __restrict__ v1,
    const int* __restrict__ r2, const int* __restrict__ c2, const float* __restrict__ v2,
    const int* __restrict__ r3, const int* __restrict__ c3, const float* __restrict__ v3,
    int nnz)
{
    const int slot = blockIdx.y;
    const int* rows; const int* cols; const float* vals;
    switch (slot) {
        case 0:  rows = r0; cols = c0; vals = v0; break;
        case 1:  rows = r1; cols = c1; vals = v1; break;
        case 2:  rows = r2; cols = c2; vals = v2; break;
        default: rows = r3; cols = c3; vals = v3; break;
    }
    const int i = blockIdx.x * 256 + threadIdx.x;
    if (i >= nnz) return;
    const int   row = rows[i];
    const int   col = cols[i];
    const float val = vals[i];
    const int gr  = slot * NROWS + row;
    const int pos = atomicAdd(&g_cnt[gr], 1);
    if (pos < CAP)
        g_bucket[(size_t)gr * CAP + pos] = make_int2(col, __float_as_int(val));
}

// ---------------------------------------------------------------------------
// Kernel 3: gather — one warp per output row (validated R4)
// ---------------------------------------------------------------------------
__global__ void __launch_bounds__(256) gather_rows(const float* __restrict__ ebs)
{
    const int wg   = (blockIdx.x * 256 + threadIdx.x) >> 5;
    const int lane = threadIdx.x & 31;
    if (wg >= NSLOT * NROWS) return;

    int cnt = g_cnt[wg];
    cnt = min(cnt, CAP);

    const int2* bk = g_bucket + (size_t)wg * CAP;
    int2 e0 = make_int2(0, 0), e1 = make_int2(0, 0);
    if (lane      < cnt) e0 = bk[lane];
    if (lane + 32 < cnt) e1 = bk[lane + 32];

    float4 acc = make_float4(0.f, 0.f, 0.f, 0.f);
    for (int j = 0; j < cnt; j++) {
        int cj, vb;
        if (j < 32) { cj = __shfl_sync(0xffffffffu, e0.x, j);
                      vb = __shfl_sync(0xffffffffu, e0.y, j); }
        else        { cj = __shfl_sync(0xffffffffu, e1.x, j - 32);
                      vb = __shfl_sync(0xffffffffu, e1.y, j - 32); }
        const float  vj = __int_as_float(vb);
        const float4 e  = *reinterpret_cast<const float4*>(ebs + (size_t)cj * DIM + lane * 4);
        acc.x += vj * e.x; acc.y += vj * e.y; acc.z += vj * e.z; acc.w += vj * e.w;
    }
    *reinterpret_cast<float4*>(g_scratch + (size_t)wg * DIM + lane * 4) = acc;
}

// ---------------------------------------------------------------------------
// Kernel 4: fused fold GEMM + gate + leaky relu, f32x2 FMA.
// Block tile 64 rows x 128 cols, 8 warps; warp tile 8 rows x 128 cols.
// Lane -> 4 cols (lane*4). A/B LDS are pure warp broadcasts (1 wf each).
// Per-warp per-k L1 cost: 8 wf (W LDG) + 4 wf (A/B) = 12 vs 16 fma-cycles
// -> fma-bound. Regs: acc 32 + W prefetch 32 + transients ~ 90.
// ---------------------------------------------------------------------------
constexpr int TR = 64;                          // rows per block
constexpr int GEMM_SMEM = 2 * TR * DIM * 4;     // As + Bs = 64 KB

__global__ void __launch_bounds__(256) fold_gemm5(
    const float* __restrict__ ebs,
    const float* __restrict__ Wsu, const float* __restrict__ Wdu,
    const float* __restrict__ Wsi, const float* __restrict__ Wdi,
    float* __restrict__ outp)
{
    extern __shared__ float sm[];
    float (*As)[DIM] = reinterpret_cast<float(*)[DIM]>(sm);
    float (*Bs)[DIM] = reinterpret_cast<float(*)[DIM]>(sm + TR * DIM);

    const int fold = blockIdx.y;
    const float* LI  = g_scratch + (size_t)(2 * fold)     * SEG;
    const float* L   = g_scratch + (size_t)(2 * fold + 1) * SEG;
    const float* ent = ebs  + (size_t)fold * SEG;
    const float* Ws  = fold ? Wsi : Wsu;
    const float* Wd  = fold ? Wdi : Wdu;
    float* out       = outp + (size_t)fold * SEG;

    const int row0 = blockIdx.x * TR;
    const int tid  = threadIdx.x;

    // Cooperative load: 64 rows x 128 cols, float4 coalesced, row-guarded.
    for (int i = tid; i < TR * (DIM / 4); i += 256) {
        const int rr = i >> 5;
        const int c4 = i & 31;
        const int grow = row0 + rr;
        float4 li = make_float4(0.f, 0.f, 0.f, 0.f);
        float4 b  = li;
        if (grow < N_USERS) {
            const size_t g = (size_t)grow * DIM + c4 * 4;
            li = *reinterpret_cast<const float4*>(LI  + g);
            const float4 ll = *reinterpret_cast<const float4*>(L   + g);
            const float4 ee = *reinterpret_cast<const float4*>(ent + g);
            b = make_float4(ll.x * ee.x, ll.y * ee.y, ll.z * ee.z, ll.w * ee.w);
        }
        *reinterpret_cast<float4*>(&As[rr][c4 * 4]) = li;
        *reinterpret_cast<float4*>(&Bs[rr][c4 * 4]) = b;
    }
    __syncthreads();

    const int lane  = tid & 31;
    const int wid   = tid >> 5;
    const int wrow0 = wid * 8;        // this warp's 8 rows
    const int colb  = lane * 4;       // this lane's 4 cols

    unsigned long long acc2[8][2];
    #pragma unroll
    for (int r = 0; r < 8; r++) { acc2[r][0] = 0ull; acc2[r][1] = 0ull; }

    #pragma unroll 1
    for (int kb = 0; kb < DIM; kb += 4) {
        // Prefetch W for 4 k values: 2 mats x ulonglong2 per k.
        ulonglong2 wsp[4], wdp[4];
        #pragma unroll
        for (int kk = 0; kk < 4; kk++) {
            wsp[kk] = *reinterpret_cast<const ulonglong2*>(Ws + (size_t)(kb + kk) * DIM + colb);
            wdp[kk] = *reinterpret_cast<const ulonglong2*>(Wd + (size_t)(kb + kk) * DIM + colb);
        }
        // Row-by-row: A/B stay transient (2 float4 live at a time).
        #pragma unroll
        for (int r = 0; r < 8; r++) {
            const float4 a4 = *reinterpret_cast<const float4*>(&As[wrow0 + r][kb]);  // broadcast
            const float4 b4 = *reinterpret_cast<const float4*>(&Bs[wrow0 + r][kb]);  // broadcast
            const float av[4] = {a4.x, a4.y, a4.z, a4.w};
            const float bv[4] = {b4.x, b4.y, b4.z, b4.w};
            #pragma unroll
            for (int kk = 0; kk < 4; kk++) {
                const unsigned long long aa = pk2(av[kk], av[kk]);
                const unsigned long long bb = pk2(bv[kk], bv[kk]);
                acc2[r][0] = fma2(aa, wsp[kk].x, acc2[r][0]);
                acc2[r][1] = fma2(aa, wsp[kk].y, acc2[r][1]);
                acc2[r][0] = fma2(bb, wdp[kk].x, acc2[r][0]);
                acc2[r][1] = fma2(bb, wdp[kk].y, acc2[r][1]);
            }
        }
    }

    #pragma unroll
    for (int r = 0; r < 8; r++) {
        const int grow = row0 + wrow0 + r;
        if (grow < N_USERS) {
            float c0, c1, c2, c3;
            upk2(acc2[r][0], c0, c1);
            upk2(acc2[r][1], c2, c3);
            float4 o;
            o.x = (c0 > 0.f) ? c0 : 0.2f * c0;
            o.y = (c1 > 0.f) ? c1 : 0.2f * c1;
            o.z = (c2 > 0.f) ? c2 : 0.2f * c2;
            o.w = (c3 > 0.f) ? c3 : 0.2f * c3;
            *reinterpret_cast<float4*>(out + (size_t)grow * DIM + colb) = o;
        }
    }
}

// ---------------------------------------------------------------------------
// Launch contract
// ---------------------------------------------------------------------------
extern "C" void kernel_launch(void* const* d_in, const int* in_sizes, int n_in,
                              void* d_out, int out_size)
{
    const float* ebs  = (const float*)d_in[0];
    const float* Wsu  = (const float*)d_in[1];
    const float* Wdu  = (const float*)d_in[2];
    const float* Wsi  = (const float*)d_in[3];
    const float* Wdi  = (const float*)d_in[4];
    const float* vLIu = (const float*)d_in[5];
    const float* vLu  = (const float*)d_in[6];
    const float* vLIi = (const float*)d_in[7];
    const float* vLi  = (const float*)d_in[8];
    const int* rLIu = (const int*)d_in[9];
    const int* cLIu = (const int*)d_in[10];
    const int* rLu  = (const int*)d_in[11];
    const int* cLu  = (const int*)d_in[12];
    const int* rLIi = (const int*)d_in[13];
    const int* cLIi = (const int*)d_in[14];
    const int* rLi  = (const int*)d_in[15];
    const int* cLi  = (const int*)d_in[16];
    float* out = (float*)d_out;

    const int nnz = in_sizes[5];

    // 1) zero counters
    zero_cnt<<<(NSLOT * NROWS + 255) / 256, 256>>>();

    // 2) scatter nnz into buckets
    {
        dim3 grid((nnz + 255) / 256, NSLOT);
        scatter_nnz<<<grid, 256>>>(rLIu, cLIu, vLIu,
                                   rLu,  cLu,  vLu,
                                   rLIi, cLIi, vLIi,
                                   rLi,  cLi,  vLi,
                                   nnz);
    }

    // 3) gather
    {
        const int total_warps = NSLOT * NROWS;
        const int blocks = (total_warps * 32 + 255) / 256;
        gather_rows<<<blocks, 256>>>(ebs);
    }

    // 4) fused fold GEMM: 64-row block tile, 8-row x 128-col warp tile
    {
        cudaFuncSetAttribute(fold_gemm5,
                             cudaFuncAttributeMaxDynamicSharedMemorySize, GEMM_SMEM);
        dim3 grid((N_USERS + TR - 1) / TR, 2);
        fold_gemm5<<<grid, 256, GEMM_SMEM>>>(ebs, Wsu, Wdu, Wsi, Wdi, out);
    }
}